// round 3
// baseline (speedup 1.0000x reference)
#include <cuda_runtime.h>
#include <cstdint>

// ---------------------------------------------------------------------------
// Quantized LeNet, B=1024. All GEMM/conv math in exact int8 via dp4a.
// Inputs (metadata order): x[1024,1,28,28] f32, w1[32,1,3,3], w2[64,32,3,3],
// wl1[4096,1600], wl2[10,4096], s_in, s_a1, s_a2, s_a3 (1-elem f32 scalars).
// Output: [1024,10] f32.
// ---------------------------------------------------------------------------

#define DEVBUF __device__ __align__(16)

__device__ unsigned g_absmax[4];                 // |w| max bits: w1,w2,wl1,wl2
DEVBUF int8_t g_w1q [32 * 9];                    // [oc][tap]
DEVBUF int8_t g_w2q [9 * 8 * 64 * 4];            // [tap][cg][oc][4 in-ch] = 18432
DEVBUF int8_t g_wl1q[4096 * 1600];               // row-major [n][k]
DEVBUF int8_t g_wl2q[10 * 4096];                 // row-major [n][k]
DEVBUF int8_t g_a1  [1024 * 13 * 13 * 32];       // conv1 out, NHWC codes [-8,7]
DEVBUF int8_t g_a2  [1024 * 1600];               // conv2 out, flattened NCHW codes
DEVBUF int8_t g_a3  [1024 * 4096];               // fc1 out, codes [0,15]

// ---------------------------------------------------------------------------
__global__ void k_init() {
    if (threadIdx.x < 4) g_absmax[threadIdx.x] = 0u;
}

__global__ void k_absmax(const float* __restrict__ w, int n, int slot) {
    float m = 0.f;
    for (int i = blockIdx.x * blockDim.x + threadIdx.x; i < n;
         i += gridDim.x * blockDim.x)
        m = fmaxf(m, fabsf(w[i]));
#pragma unroll
    for (int o = 16; o > 0; o >>= 1)
        m = fmaxf(m, __shfl_xor_sync(0xffffffffu, m, o));
    if ((threadIdx.x & 31) == 0)
        atomicMax(&g_absmax[slot], __float_as_uint(m));  // nonneg float bits
}

__device__ __forceinline__ int8_t* qdst(int slot) {
    switch (slot) {
        case 0:  return g_w1q;
        case 2:  return g_wl1q;
        default: return g_wl2q;
    }
}

// symmetric narrow weight fake-quant -> int8 codes in [-7,7]
__global__ void k_quant_plain(const float* __restrict__ w, int n, int slot) {
    float s = __fdiv_rn(__uint_as_float(g_absmax[slot]), 7.0f);
    int8_t* q = qdst(slot);
    for (int i = blockIdx.x * blockDim.x + threadIdx.x; i < n;
         i += gridDim.x * blockDim.x) {
        float t = rintf(__fdiv_rn(w[i], s));
        t = fminf(fmaxf(t, -7.f), 7.f);
        q[i] = (int8_t)t;
    }
}

// w2 [oc][ci][3][3] -> g_w2q[((tap*8+cg)*64 + oc)*4 + clo],  ci = cg*4+clo
__global__ void k_quant_w2(const float* __restrict__ w2) {
    float s = __fdiv_rn(__uint_as_float(g_absmax[1]), 7.0f);
    int i = blockIdx.x * blockDim.x + threadIdx.x;
    if (i >= 64 * 32 * 9) return;
    int o = i / 288, rem = i % 288, ci = rem / 9, tap = rem % 9;
    float t = rintf(__fdiv_rn(w2[i], s));
    t = fminf(fmaxf(t, -7.f), 7.f);
    g_w2q[((tap * 8 + (ci >> 2)) * 64 + o) * 4 + (ci & 3)] = (int8_t)t;
}

// ---------------------------------------------------------------------------
// conv1 fused: quantize x -> 3x3 conv (1ch) -> relu-quant(s_a1) -> pool 2x2
//              -> requant(s_in) -> NHWC int8.  One block per image.
__global__ void __launch_bounds__(256) k_conv1(const float* __restrict__ x,
                                               const float* __restrict__ ps_in,
                                               const float* __restrict__ ps_a1) {
    __shared__ int8_t sx[28 * 28];
    __shared__ int8_t sw[32 * 9];
    int b = blockIdx.x, tid = threadIdx.x;
    float s_in = ps_in[0], s_a1 = ps_a1[0];
    float s_w = __fdiv_rn(__uint_as_float(g_absmax[0]), 7.0f);
    const float* xb = x + b * 784;
    for (int i = tid; i < 784; i += 256) {
        float t = rintf(__fdiv_rn(xb[i], s_in));
        t = fminf(fmaxf(t, -8.f), 7.f);
        sx[i] = (int8_t)t;
    }
    for (int i = tid; i < 288; i += 256) sw[i] = g_w1q[i];
    __syncthreads();

    float sf = s_in * s_w;
    for (int idx = tid; idx < 32 * 13 * 13; idx += 256) {
        int c = idx / 169, rem = idx % 169, ph = rem / 13, pw = rem % 13;
        int qmax = 0;
#pragma unroll
        for (int dy = 0; dy < 2; dy++)
#pragma unroll
            for (int dx = 0; dx < 2; dx++) {
                int oy = 2 * ph + dy, ox = 2 * pw + dx;
                int acc = 0;
#pragma unroll
                for (int ky = 0; ky < 3; ky++)
#pragma unroll
                    for (int kx = 0; kx < 3; kx++)
                        acc += (int)sx[(oy + ky) * 28 + ox + kx] *
                               (int)sw[c * 9 + ky * 3 + kx];
                float v = (float)acc * sf;
                float t = rintf(__fdiv_rn(v, s_a1));
                t = fminf(fmaxf(t, 0.f), 15.f);
                int q = (int)t;
                qmax = max(qmax, q);
            }
        float v2 = (float)qmax * s_a1;
        float t2 = rintf(__fdiv_rn(v2, s_in));
        t2 = fminf(fmaxf(t2, -8.f), 7.f);
        g_a1[(b * 169 + ph * 13 + pw) * 32 + c] = (int8_t)t2;
    }
}

// ---------------------------------------------------------------------------
// conv2 fused: 3x3x32 conv (dp4a) -> relu-quant(s_a2) -> pool -> requant(s_in)
// One block per image. Thread = (pool window, 8-out-channel group): the 2x2
// conv positions of a pool window live in one thread, so pooling is local.
__global__ void __launch_bounds__(256) k_conv2(const float* __restrict__ ps_in,
                                               const float* __restrict__ ps_a2) {
    __shared__ __align__(16) int8_t sa[5408];    // 13*13*32 NHWC
    __shared__ __align__(16) int8_t swq[18432];  // [tap][cg][oc][4]
    int b = blockIdx.x, tid = threadIdx.x;
    {
        const int4* src = (const int4*)(g_a1 + b * 5408);
        int4* dst = (int4*)sa;
        for (int i = tid; i < 338; i += 256) dst[i] = src[i];
        const int4* ws = (const int4*)g_w2q;
        int4* wd = (int4*)swq;
        for (int i = tid; i < 1152; i += 256) wd[i] = ws[i];
    }
    __syncthreads();
    if (tid >= 200) return;

    float s_in = ps_in[0], s_a2 = ps_a2[0];
    float s_w = __fdiv_rn(__uint_as_float(g_absmax[1]), 7.0f);
    float sf = s_in * s_w;

    int win = tid >> 3, tn = tid & 7;     // 25 windows x 8 channel-groups
    int ph = win / 5, pw = win % 5;
    const int* aw = (const int*)sa;
    const int* ww = (const int*)swq;

    int acc[4][8];
#pragma unroll
    for (int i = 0; i < 4; i++)
#pragma unroll
        for (int j = 0; j < 8; j++) acc[i][j] = 0;

#pragma unroll
    for (int ky = 0; ky < 3; ky++) {
#pragma unroll
        for (int kx = 0; kx < 3; kx++) {
            int base[4];
#pragma unroll
            for (int i = 0; i < 4; i++) {
                int dy = i >> 1, dx = i & 1;
                base[i] = ((2 * ph + dy + ky) * 13 + (2 * pw + dx + kx)) * 8;
            }
            int k9 = ky * 3 + kx;
#pragma unroll
            for (int cg = 0; cg < 8; cg++) {
                int av[4];
#pragma unroll
                for (int i = 0; i < 4; i++) av[i] = aw[base[i] + cg];
#pragma unroll
                for (int j = 0; j < 8; j++) {
                    int wv = ww[(k9 * 8 + cg) * 64 + tn * 8 + j];
#pragma unroll
                    for (int i = 0; i < 4; i++)
                        acc[i][j] = __dp4a(av[i], wv, acc[i][j]);
                }
            }
        }
    }
#pragma unroll
    for (int j = 0; j < 8; j++) {
        int qm = 0;
#pragma unroll
        for (int i = 0; i < 4; i++) {
            float v = (float)acc[i][j] * sf;
            float t = rintf(__fdiv_rn(v, s_a2));
            t = fminf(fmaxf(t, 0.f), 15.f);
            qm = max(qm, (int)t);
        }
        float v2 = (float)qm * s_a2;
        float t2 = rintf(__fdiv_rn(v2, s_in));
        t2 = fminf(fmaxf(t2, -8.f), 7.f);
        int c = tn * 8 + j;
        g_a2[b * 1600 + c * 25 + ph * 5 + pw] = (int8_t)t2;  // NCHW flatten
    }
}

// ---------------------------------------------------------------------------
// FC1: [1024,1600] x [4096,1600]^T, dp4a GEMM. BM=128 BN=64, thread-tile 8x4.
// smem staged k-word-major (transposed): A reads broadcast, B reads stride-1
// (columns assigned n = n0 + tx + 16*j) -> conflict-free LDS.
__global__ void __launch_bounds__(256) k_fc1(const float* __restrict__ ps_in,
                                             const float* __restrict__ ps_a3) {
    __shared__ __align__(16) int As[16][128];  // [kword][row]   8KB
    __shared__ __align__(16) int Bs[16][64];   // [kword][col]   4KB
    int tid = threadIdx.x;
    int tx = tid & 15, ty = tid >> 4;
    int m0 = blockIdx.y * 128, n0 = blockIdx.x * 64;
    const int8_t* Ag = g_a2 + m0 * 1600;
    const int8_t* Bg = g_wl1q + n0 * 1600;

    int acc[8][4];
#pragma unroll
    for (int i = 0; i < 8; i++)
#pragma unroll
        for (int j = 0; j < 4; j++) acc[i][j] = 0;

    for (int ch = 0; ch < 25; ch++) {  // K = 25 chunks of 64 bytes
        for (int i = tid; i < 512; i += 256) {
            int r = i >> 2, wg = i & 3;
            int4 v = *((const int4*)(Ag + r * 1600 + ch * 64) + wg);
            As[wg * 4 + 0][r] = v.x;
            As[wg * 4 + 1][r] = v.y;
            As[wg * 4 + 2][r] = v.z;
            As[wg * 4 + 3][r] = v.w;
        }
        if (tid < 256) {
            int r = tid >> 2, wg = tid & 3;
            int4 v = *((const int4*)(Bg + r * 1600 + ch * 64) + wg);
            Bs[wg * 4 + 0][r] = v.x;
            Bs[wg * 4 + 1][r] = v.y;
            Bs[wg * 4 + 2][r] = v.z;
            Bs[wg * 4 + 3][r] = v.w;
        }
        __syncthreads();
#pragma unroll 4
        for (int kw = 0; kw < 16; kw++) {
            const int4* ap = (const int4*)(&As[kw][ty * 8]);
            int4 a0 = ap[0], a1 = ap[1];
            int a_[8] = {a0.x, a0.y, a0.z, a0.w, a1.x, a1.y, a1.z, a1.w};
            int b_[4];
#pragma unroll
            for (int j = 0; j < 4; j++) b_[j] = Bs[kw][tx + 16 * j];
#pragma unroll
            for (int i = 0; i < 8; i++)
#pragma unroll
                for (int j = 0; j < 4; j++)
                    acc[i][j] = __dp4a(a_[i], b_[j], acc[i][j]);
        }
        __syncthreads();
    }

    float s_in = ps_in[0], s_a3 = ps_a3[0];
    float s_w = __fdiv_rn(__uint_as_float(g_absmax[2]), 7.0f);
    float sf = s_in * s_w;
#pragma unroll
    for (int i = 0; i < 8; i++) {
        int m = m0 + ty * 8 + i;
#pragma unroll
        for (int j = 0; j < 4; j++) {
            int n = n0 + tx + 16 * j;
            float v = (float)acc[i][j] * sf;
            float t = rintf(__fdiv_rn(v, s_a3));
            t = fminf(fmaxf(t, 0.f), 15.f);
            g_a3[m * 4096 + n] = (int8_t)t;
        }
    }
}

// ---------------------------------------------------------------------------
// FC2: [1024,4096] x [10,4096]^T -> f32 out. One block per image row.
__global__ void __launch_bounds__(128) k_fc2(float* __restrict__ out,
                                             const float* __restrict__ ps_a3) {
    __shared__ int red[4][10];
    int b = blockIdx.x, tid = threadIdx.x;
    const int* aw = (const int*)g_a3 + b * 1024;
    const int* wp = (const int*)g_wl2q;
    int acc[10];
#pragma unroll
    for (int n = 0; n < 10; n++) acc[n] = 0;
    for (int k = tid; k < 1024; k += 128) {
        int a = aw[k];
#pragma unroll
        for (int n = 0; n < 10; n++) acc[n] = __dp4a(a, wp[n * 1024 + k], acc[n]);
    }
#pragma unroll
    for (int n = 0; n < 10; n++)
#pragma unroll
        for (int o = 16; o > 0; o >>= 1)
            acc[n] += __shfl_xor_sync(0xffffffffu, acc[n], o);
    if ((tid & 31) == 0) {
        int w = tid >> 5;
#pragma unroll
        for (int n = 0; n < 10; n++) red[w][n] = acc[n];
    }
    __syncthreads();
    if (tid < 10) {
        int s = red[0][tid] + red[1][tid] + red[2][tid] + red[3][tid];
        float s_a3 = ps_a3[0];
        float s_w = __fdiv_rn(__uint_as_float(g_absmax[3]), 7.0f);
        out[b * 10 + tid] = (float)s * (s_a3 * s_w);
    }
}

// ---------------------------------------------------------------------------
extern "C" void kernel_launch(void* const* d_in, const int* in_sizes, int n_in,
                              void* d_out, int out_size) {
    const float* x    = (const float*)d_in[0];
    const float* w1   = (const float*)d_in[1];
    const float* w2   = (const float*)d_in[2];
    const float* wl1  = (const float*)d_in[3];
    const float* wl2  = (const float*)d_in[4];
    const float* s_in = (const float*)d_in[5];
    const float* s_a1 = (const float*)d_in[6];
    const float* s_a2 = (const float*)d_in[7];
    const float* s_a3 = (const float*)d_in[8];
    float* out = (float*)d_out;
    (void)in_sizes; (void)n_in; (void)out_size;

    k_init<<<1, 32>>>();
    k_absmax<<<2, 256>>>(w1, 32 * 9, 0);
    k_absmax<<<72, 256>>>(w2, 64 * 32 * 9, 1);
    k_absmax<<<1024, 256>>>(wl1, 4096 * 1600, 2);
    k_absmax<<<160, 256>>>(wl2, 10 * 4096, 3);

    k_quant_plain<<<2, 256>>>(w1, 32 * 9, 0);
    k_quant_w2<<<(64 * 32 * 9 + 255) / 256, 256>>>(w2);
    k_quant_plain<<<2048, 256>>>(wl1, 4096 * 1600, 2);
    k_quant_plain<<<160, 256>>>(wl2, 10 * 4096, 3);

    k_conv1<<<1024, 256>>>(x, s_in, s_a1);
    k_conv2<<<1024, 256>>>(s_in, s_a2);
    k_fc1<<<dim3(4096 / 64, 1024 / 128), 256>>>(s_in, s_a3);
    k_fc2<<<1024, 128>>>(out, s_a3);
}

// round 4
// speedup vs baseline: 1.1762x; 1.1762x over previous
#include <cuda_runtime.h>
#include <cstdint>

// ---------------------------------------------------------------------------
// Quantized LeNet, B=1024. convs in dp4a, FC1 in int8 tensor-core mma.sync.
// Inputs: x[1024,1,28,28] f32, w1[32,1,3,3], w2[64,32,3,3], wl1[4096,1600],
// wl2[10,4096], s_in, s_a1, s_a2, s_a3. Output: [1024,10] f32.
// ---------------------------------------------------------------------------

#define DEVBUF __device__ __align__(16)

__device__ unsigned g_absmax[4];                 // |w| max bits: w1,w2,wl1,wl2
DEVBUF int8_t g_w1q [32 * 9];                    // [oc][tap]
DEVBUF int8_t g_w2q [9 * 8 * 64 * 4];            // [tap][cg][oc][4 in-ch]
DEVBUF int8_t g_wl1q[4096 * 1600];               // row-major [n][k]
DEVBUF int8_t g_wl2q[10 * 4096];                 // row-major [n][k]
DEVBUF int8_t g_a1  [1024 * 13 * 13 * 32];       // conv1 out, NHWC codes [-8,7]
DEVBUF int8_t g_a2  [1024 * 1600];               // conv2 out, NCHW-flat codes
DEVBUF int8_t g_a3  [1024 * 4096];               // fc1 out, codes [0,15]

// ---------------------------------------------------------------------------
__global__ void k_init() {
    if (threadIdx.x < 4) g_absmax[threadIdx.x] = 0u;
}

// One kernel, all four abs-max reductions. float4 loads for bandwidth.
__global__ void __launch_bounds__(256) k_absmax_all(
        const float* __restrict__ w1, const float* __restrict__ w2,
        const float* __restrict__ wl1, const float* __restrict__ wl2) {
    int b = blockIdx.x, tid = threadIdx.x;
    float m = 0.f;
    int slot;
    if (b < 2048) {                               // wl1: 1638400 float4
        slot = 2;
        const float4* p = (const float4*)wl1;
        for (int i = b * 256 + tid; i < 1638400; i += 2048 * 256) {
            float4 v = p[i];
            m = fmaxf(fmaxf(fabsf(v.x), fabsf(v.y)),
                      fmaxf(fabsf(v.z), fabsf(v.w)));
        }
    } else if (b < 2088) {                        // wl2: 10240 float4
        slot = 3;
        float4 v = ((const float4*)wl2)[(b - 2048) * 256 + tid];
        m = fmaxf(fmaxf(fabsf(v.x), fabsf(v.y)), fmaxf(fabsf(v.z), fabsf(v.w)));
    } else if (b < 2106) {                        // w2: 4608 float4
        slot = 1;
        float4 v = ((const float4*)w2)[(b - 2088) * 256 + tid];
        m = fmaxf(fmaxf(fabsf(v.x), fabsf(v.y)), fmaxf(fabsf(v.z), fabsf(v.w)));
    } else {                                      // w1: 72 float4
        slot = 0;
        if (tid < 72) {
            float4 v = ((const float4*)w1)[tid];
            m = fmaxf(fmaxf(fabsf(v.x), fabsf(v.y)),
                      fmaxf(fabsf(v.z), fabsf(v.w)));
        }
    }
#pragma unroll
    for (int o = 16; o > 0; o >>= 1)
        m = fmaxf(m, __shfl_xor_sync(0xffffffffu, m, o));
    if ((tid & 31) == 0)
        atomicMax(&g_absmax[slot], __float_as_uint(m));  // nonneg float bits
}

__device__ __forceinline__ int8_t qw7(float x, float s) {
    float t = rintf(__fdiv_rn(x, s));
    return (int8_t)fminf(fmaxf(t, -7.f), 7.f);
}

// One kernel, all weight quantizations (+ w2 relayout).
__global__ void __launch_bounds__(256) k_quant_all(
        const float* __restrict__ w1, const float* __restrict__ w2,
        const float* __restrict__ wl1, const float* __restrict__ wl2) {
    int b = blockIdx.x, tid = threadIdx.x;
    if (b < 6400) {                               // wl1 char4
        float s = __fdiv_rn(__uint_as_float(g_absmax[2]), 7.0f);
        int i = b * 256 + tid;
        float4 v = ((const float4*)wl1)[i];
        char4 o;
        o.x = qw7(v.x, s); o.y = qw7(v.y, s);
        o.z = qw7(v.z, s); o.w = qw7(v.w, s);
        ((char4*)g_wl1q)[i] = o;
    } else if (b < 6440) {                        // wl2 char4
        float s = __fdiv_rn(__uint_as_float(g_absmax[3]), 7.0f);
        int i = (b - 6400) * 256 + tid;
        float4 v = ((const float4*)wl2)[i];
        char4 o;
        o.x = qw7(v.x, s); o.y = qw7(v.y, s);
        o.z = qw7(v.z, s); o.w = qw7(v.w, s);
        ((char4*)g_wl2q)[i] = o;
    } else if (b < 6512) {                        // w2 relayout (scalar)
        float s = __fdiv_rn(__uint_as_float(g_absmax[1]), 7.0f);
        int i = (b - 6440) * 256 + tid;           // < 18432
        int o = i / 288, rem = i % 288, ci = rem / 9, tap = rem % 9;
        g_w2q[((tap * 8 + (ci >> 2)) * 64 + o) * 4 + (ci & 3)] = qw7(w2[i], s);
    } else {                                      // w1
        float s = __fdiv_rn(__uint_as_float(g_absmax[0]), 7.0f);
        for (int i = tid; i < 288; i += 256) g_w1q[i] = qw7(w1[i], s);
    }
}

// ---------------------------------------------------------------------------
// conv1 fused: quantize x -> 3x3 conv (1ch) -> relu-quant(s_a1) -> pool 2x2
//              -> requant(s_in) -> NHWC int8.  One block per image.
__global__ void __launch_bounds__(256) k_conv1(const float* __restrict__ x,
                                               const float* __restrict__ ps_in,
                                               const float* __restrict__ ps_a1) {
    __shared__ int8_t sx[28 * 28];
    __shared__ int8_t sw[32 * 9];
    int b = blockIdx.x, tid = threadIdx.x;
    float s_in = ps_in[0], s_a1 = ps_a1[0];
    float s_w = __fdiv_rn(__uint_as_float(g_absmax[0]), 7.0f);
    const float* xb = x + b * 784;
    for (int i = tid; i < 784; i += 256) {
        float t = rintf(__fdiv_rn(xb[i], s_in));
        t = fminf(fmaxf(t, -8.f), 7.f);
        sx[i] = (int8_t)t;
    }
    for (int i = tid; i < 288; i += 256) sw[i] = g_w1q[i];
    __syncthreads();

    float sf = s_in * s_w;
    for (int idx = tid; idx < 32 * 13 * 13; idx += 256) {
        int c = idx / 169, rem = idx % 169, ph = rem / 13, pw = rem % 13;
        int qmax = 0;
#pragma unroll
        for (int dy = 0; dy < 2; dy++)
#pragma unroll
            for (int dx = 0; dx < 2; dx++) {
                int oy = 2 * ph + dy, ox = 2 * pw + dx;
                int acc = 0;
#pragma unroll
                for (int ky = 0; ky < 3; ky++)
#pragma unroll
                    for (int kx = 0; kx < 3; kx++)
                        acc += (int)sx[(oy + ky) * 28 + ox + kx] *
                               (int)sw[c * 9 + ky * 3 + kx];
                float v = (float)acc * sf;
                float t = rintf(__fdiv_rn(v, s_a1));
                t = fminf(fmaxf(t, 0.f), 15.f);
                qmax = max(qmax, (int)t);
            }
        float v2 = (float)qmax * s_a1;
        float t2 = rintf(__fdiv_rn(v2, s_in));
        t2 = fminf(fmaxf(t2, -8.f), 7.f);
        g_a1[(b * 169 + ph * 13 + pw) * 32 + c] = (int8_t)t2;
    }
}

// ---------------------------------------------------------------------------
// conv2 fused (dp4a): 3x3x32 conv -> relu-quant -> pool -> requant -> g_a2.
__global__ void __launch_bounds__(256) k_conv2(const float* __restrict__ ps_in,
                                               const float* __restrict__ ps_a2) {
    __shared__ __align__(16) int8_t sa[5408];    // 13*13*32 NHWC
    __shared__ __align__(16) int8_t swq[18432];  // [tap][cg][oc][4]
    int b = blockIdx.x, tid = threadIdx.x;
    {
        const int4* src = (const int4*)(g_a1 + b * 5408);
        int4* dst = (int4*)sa;
        for (int i = tid; i < 338; i += 256) dst[i] = src[i];
        const int4* ws = (const int4*)g_w2q;
        int4* wd = (int4*)swq;
        for (int i = tid; i < 1152; i += 256) wd[i] = ws[i];
    }
    __syncthreads();
    if (tid >= 200) return;

    float s_in = ps_in[0], s_a2 = ps_a2[0];
    float s_w = __fdiv_rn(__uint_as_float(g_absmax[1]), 7.0f);
    float sf = s_in * s_w;

    int win = tid >> 3, tn = tid & 7;     // 25 windows x 8 channel-groups
    int ph = win / 5, pw = win % 5;
    const int* aw = (const int*)sa;
    const int* ww = (const int*)swq;

    int acc[4][8];
#pragma unroll
    for (int i = 0; i < 4; i++)
#pragma unroll
        for (int j = 0; j < 8; j++) acc[i][j] = 0;

#pragma unroll
    for (int ky = 0; ky < 3; ky++) {
#pragma unroll
        for (int kx = 0; kx < 3; kx++) {
            int base[4];
#pragma unroll
            for (int i = 0; i < 4; i++) {
                int dy = i >> 1, dx = i & 1;
                base[i] = ((2 * ph + dy + ky) * 13 + (2 * pw + dx + kx)) * 8;
            }
            int k9 = ky * 3 + kx;
#pragma unroll
            for (int cg = 0; cg < 8; cg++) {
                int av[4];
#pragma unroll
                for (int i = 0; i < 4; i++) av[i] = aw[base[i] + cg];
#pragma unroll
                for (int j = 0; j < 8; j++) {
                    int wv = ww[(k9 * 8 + cg) * 64 + tn * 8 + j];
#pragma unroll
                    for (int i = 0; i < 4; i++)
                        acc[i][j] = __dp4a(av[i], wv, acc[i][j]);
                }
            }
        }
    }
#pragma unroll
    for (int j = 0; j < 8; j++) {
        int qm = 0;
#pragma unroll
        for (int i = 0; i < 4; i++) {
            float v = (float)acc[i][j] * sf;
            float t = rintf(__fdiv_rn(v, s_a2));
            t = fminf(fmaxf(t, 0.f), 15.f);
            qm = max(qm, (int)t);
        }
        float v2 = (float)qm * s_a2;
        float t2 = rintf(__fdiv_rn(v2, s_in));
        t2 = fminf(fmaxf(t2, -8.f), 7.f);
        int c = tn * 8 + j;
        g_a2[b * 1600 + c * 25 + ph * 5 + pw] = (int8_t)t2;
    }
}

// ---------------------------------------------------------------------------
// FC1 via int8 tensor cores: mma.sync.m16n8k32.s8. BM=128 BN=128 BK=64.
// smem layout: 16-byte "planes" per row, plane index swizzled p^((row>>1)&3)
// -> STS.128 staging and ldmatrix.x4 loads both bank-conflict-free.
// ---------------------------------------------------------------------------
__device__ __forceinline__ void ldm_x4(uint32_t addr, uint32_t* r) {
    asm volatile("ldmatrix.sync.aligned.m8n8.x4.shared.b16 {%0,%1,%2,%3}, [%4];"
                 : "=r"(r[0]), "=r"(r[1]), "=r"(r[2]), "=r"(r[3]) : "r"(addr));
}

__device__ __forceinline__ void mma_s8(int* c, const uint32_t* a,
                                       uint32_t b0, uint32_t b1) {
    asm volatile(
        "mma.sync.aligned.m16n8k32.row.col.s32.s8.s8.s32 "
        "{%0,%1,%2,%3}, {%4,%5,%6,%7}, {%8,%9}, {%0,%1,%2,%3};"
        : "+r"(c[0]), "+r"(c[1]), "+r"(c[2]), "+r"(c[3])
        : "r"(a[0]), "r"(a[1]), "r"(a[2]), "r"(a[3]), "r"(b0), "r"(b1));
}

__global__ void __launch_bounds__(256, 2) k_fc1(const float* __restrict__ ps_in,
                                                const float* __restrict__ ps_a3) {
    __shared__ __align__(16) int8_t As[128 * 64];  // [row][plane*16B] swizzled
    __shared__ __align__(16) int8_t Bs[128 * 64];
    int tid = threadIdx.x, lane = tid & 31, wid = tid >> 5;
    int wm = wid >> 2, wn = wid & 3;               // warp tile 64x32
    int m0 = blockIdx.y * 128, n0 = blockIdx.x * 128;

    // staging: thread handles (srow, sp) and (srow+64, sp); 64B/row coalesced
    int srow = tid >> 2, sp = tid & 3;
    int spp = sp ^ ((srow >> 1) & 3);
    const int8_t* agp = g_a2 + (m0 + srow) * 1600 + sp * 16;
    const int8_t* bgp = g_wl1q + (n0 + srow) * 1600 + sp * 16;
    int soff = (srow * 4 + spp) * 16;              // +4096 for row+64

    uint32_t sm_a = (uint32_t)__cvta_generic_to_shared(As);
    uint32_t sm_b = (uint32_t)__cvta_generic_to_shared(Bs);

    int acc[4][4][4];                              // [mt][nt][frag]
#pragma unroll
    for (int i = 0; i < 4; i++)
#pragma unroll
        for (int j = 0; j < 4; j++)
#pragma unroll
            for (int k = 0; k < 4; k++) acc[i][j][k] = 0;

    int rl = lane & 15, ph = lane >> 4;
    // precompute ldmatrix addresses (constant across chunks)
    uint32_t a_addr[4], b_addr[2];
#pragma unroll
    for (int mt = 0; mt < 4; mt++) {
        int r = wm * 64 + mt * 16 + rl;
        int pp = ph ^ ((r >> 1) & 3);              // ks adds ^2 on plane
        a_addr[mt] = sm_a + (r * 4 + pp) * 16;
    }
#pragma unroll
    for (int bt = 0; bt < 2; bt++) {
        int n = wn * 32 + bt * 16 + rl;
        int pp = ph ^ ((n >> 1) & 3);
        b_addr[bt] = sm_b + (n * 4 + pp) * 16;
    }
    // ks=1 flips plane bit 1: addr ^= (2*16) in the plane slot -> xor 32 bytes
    // within the 64B row: plane index p -> p^2 means addr16 ^= 2 -> byte ^= 32.

    int4 ra0 = *(const int4*)agp;
    int4 ra1 = *(const int4*)(agp + 64 * 1600);
    int4 rb0 = *(const int4*)bgp;
    int4 rb1 = *(const int4*)(bgp + 64 * 1600);

    for (int ch = 0; ch < 25; ch++) {
        __syncthreads();
        *(int4*)(As + soff) = ra0;
        *(int4*)(As + soff + 4096) = ra1;
        *(int4*)(Bs + soff) = rb0;
        *(int4*)(Bs + soff + 4096) = rb1;
        __syncthreads();
        agp += 64; bgp += 64;
        if (ch < 24) {
            ra0 = *(const int4*)agp;
            ra1 = *(const int4*)(agp + 64 * 1600);
            rb0 = *(const int4*)bgp;
            rb1 = *(const int4*)(bgp + 64 * 1600);
        }
#pragma unroll
        for (int ks = 0; ks < 2; ks++) {
            uint32_t kx = ks ? 32u : 0u;           // plane ^2 == byte ^32
            uint32_t af[4][4], bf[2][4];
#pragma unroll
            for (int mt = 0; mt < 4; mt++) ldm_x4(a_addr[mt] ^ kx, af[mt]);
#pragma unroll
            for (int bt = 0; bt < 2; bt++) ldm_x4(b_addr[bt] ^ kx, bf[bt]);
#pragma unroll
            for (int mt = 0; mt < 4; mt++)
#pragma unroll
                for (int nt = 0; nt < 4; nt++)
                    mma_s8(acc[mt][nt], af[mt],
                           bf[nt >> 1][nt & 1], bf[nt >> 1][(nt & 1) + 2]);
        }
    }

    float s_in = ps_in[0], s_a3 = ps_a3[0];
    float s_w = __fdiv_rn(__uint_as_float(g_absmax[2]), 7.0f);
    float sf = s_in * s_w;
    int g = lane >> 2, t4 = lane & 3;
#pragma unroll
    for (int mt = 0; mt < 4; mt++) {
#pragma unroll
        for (int nt = 0; nt < 4; nt++) {
            int mrow = m0 + wm * 64 + mt * 16 + g;
            int ncol = n0 + wn * 32 + nt * 8 + t4 * 2;
#pragma unroll
            for (int h = 0; h < 2; h++) {          // h=0: row, h=1: row+8
                char2 o;
                float v0 = (float)acc[mt][nt][2 * h] * sf;
                float t0 = rintf(__fdiv_rn(v0, s_a3));
                o.x = (int8_t)fminf(fmaxf(t0, 0.f), 15.f);
                float v1 = (float)acc[mt][nt][2 * h + 1] * sf;
                float t1 = rintf(__fdiv_rn(v1, s_a3));
                o.y = (int8_t)fminf(fmaxf(t1, 0.f), 15.f);
                *(char2*)(g_a3 + (mrow + 8 * h) * 4096 + ncol) = o;
            }
        }
    }
}

// ---------------------------------------------------------------------------
// FC2: [1024,4096] x [10,4096]^T -> f32 out. One block per image row.
__global__ void __launch_bounds__(128) k_fc2(float* __restrict__ out,
                                             const float* __restrict__ ps_a3) {
    __shared__ int red[4][10];
    int b = blockIdx.x, tid = threadIdx.x;
    const int* aw = (const int*)g_a3 + b * 1024;
    const int* wp = (const int*)g_wl2q;
    int acc[10];
#pragma unroll
    for (int n = 0; n < 10; n++) acc[n] = 0;
    for (int k = tid; k < 1024; k += 128) {
        int a = aw[k];
#pragma unroll
        for (int n = 0; n < 10; n++) acc[n] = __dp4a(a, wp[n * 1024 + k], acc[n]);
    }
#pragma unroll
    for (int n = 0; n < 10; n++)
#pragma unroll
        for (int o = 16; o > 0; o >>= 1)
            acc[n] += __shfl_xor_sync(0xffffffffu, acc[n], o);
    if ((tid & 31) == 0) {
        int w = tid >> 5;
#pragma unroll
        for (int n = 0; n < 10; n++) red[w][n] = acc[n];
    }
    __syncthreads();
    if (tid < 10) {
        int s = red[0][tid] + red[1][tid] + red[2][tid] + red[3][tid];
        float s_a3 = ps_a3[0];
        float s_w = __fdiv_rn(__uint_as_float(g_absmax[3]), 7.0f);
        out[b * 10 + tid] = (float)s * (s_a3 * s_w);
    }
}

// ---------------------------------------------------------------------------
extern "C" void kernel_launch(void* const* d_in, const int* in_sizes, int n_in,
                              void* d_out, int out_size) {
    const float* x    = (const float*)d_in[0];
    const float* w1   = (const float*)d_in[1];
    const float* w2   = (const float*)d_in[2];
    const float* wl1  = (const float*)d_in[3];
    const float* wl2  = (const float*)d_in[4];
    const float* s_in = (const float*)d_in[5];
    const float* s_a1 = (const float*)d_in[6];
    const float* s_a2 = (const float*)d_in[7];
    const float* s_a3 = (const float*)d_in[8];
    float* out = (float*)d_out;
    (void)in_sizes; (void)n_in; (void)out_size;

    k_init<<<1, 32>>>();
    k_absmax_all<<<2107, 256>>>(w1, w2, wl1, wl2);
    k_quant_all<<<6513, 256>>>(w1, w2, wl1, wl2);
    k_conv1<<<1024, 256>>>(x, s_in, s_a1);
    k_conv2<<<1024, 256>>>(s_in, s_a2);
    k_fc1<<<dim3(4096 / 128, 1024 / 128), 256>>>(s_in, s_a3);
    k_fc2<<<1024, 128>>>(out, s_a3);
}

// round 5
// speedup vs baseline: 1.4791x; 1.2576x over previous
#include <cuda_runtime.h>
#include <cstdint>

// ---------------------------------------------------------------------------
// Quantized LeNet, B=1024. conv1/conv2 dp4a, FC1 int8 mma.sync.
// Pool-max commutes with monotone quantization -> integer max first, then one
// quant chain; quant chains precomputed into integer->int8 LUTs (exact).
// ---------------------------------------------------------------------------

#define DEVBUF __device__ __align__(16)

__device__ unsigned g_absmax[4];                 // |w| max bits: w1,w2,wl1,wl2
DEVBUF int8_t g_w1q [32 * 9];                    // [oc][tap]
DEVBUF int8_t g_w2q [9 * 8 * 64 * 4];            // [tap][cg][oc][4 in-ch]
DEVBUF int8_t g_wl1q[4096 * 1600];               // row-major [n][k]
DEVBUF int8_t g_wl2q[10 * 4096];                 // row-major [n][k]
DEVBUF int8_t g_a1  [1024 * 13 * 13 * 32];       // conv1 out, NHWC codes [-8,7]
DEVBUF int8_t g_a2  [1024 * 1600];               // conv2 out, NCHW-flat codes
DEVBUF int8_t g_a3  [1024 * 4096];               // fc1 out, codes [0,15]
DEVBUF int8_t g_lut1[1009];                      // conv1 acc -> code  (+504)
DEVBUF int8_t g_lut2[32257];                     // conv2 acc -> code  (+16128)
DEVBUF int8_t g_lut3[179201];                    // fc1  acc -> code  (+89600)

// ---------------------------------------------------------------------------
__global__ void k_init() {
    if (threadIdx.x < 4) g_absmax[threadIdx.x] = 0u;
}

__global__ void __launch_bounds__(256) k_absmax_all(
        const float* __restrict__ w1, const float* __restrict__ w2,
        const float* __restrict__ wl1, const float* __restrict__ wl2) {
    int b = blockIdx.x, tid = threadIdx.x;
    float m = 0.f;
    int slot;
    if (b < 2048) {                               // wl1: 1638400 float4
        slot = 2;
        const float4* p = (const float4*)wl1;
        for (int i = b * 256 + tid; i < 1638400; i += 2048 * 256) {
            float4 v = p[i];
            m = fmaxf(fmaxf(fabsf(v.x), fabsf(v.y)),
                      fmaxf(fabsf(v.z), fabsf(v.w)));
        }
    } else if (b < 2088) {                        // wl2: 10240 float4
        slot = 3;
        float4 v = ((const float4*)wl2)[(b - 2048) * 256 + tid];
        m = fmaxf(fmaxf(fabsf(v.x), fabsf(v.y)), fmaxf(fabsf(v.z), fabsf(v.w)));
    } else if (b < 2106) {                        // w2: 4608 float4
        slot = 1;
        float4 v = ((const float4*)w2)[(b - 2088) * 256 + tid];
        m = fmaxf(fmaxf(fabsf(v.x), fabsf(v.y)), fmaxf(fabsf(v.z), fabsf(v.w)));
    } else {                                      // w1: 72 float4
        slot = 0;
        if (tid < 72) {
            float4 v = ((const float4*)w1)[tid];
            m = fmaxf(fmaxf(fabsf(v.x), fabsf(v.y)),
                      fmaxf(fabsf(v.z), fabsf(v.w)));
        }
    }
#pragma unroll
    for (int o = 16; o > 0; o >>= 1)
        m = fmaxf(m, __shfl_xor_sync(0xffffffffu, m, o));
    if ((tid & 31) == 0)
        atomicMax(&g_absmax[slot], __float_as_uint(m));
}

__device__ __forceinline__ int8_t qw7(float x, float s) {
    float t = rintf(__fdiv_rn(x, s));
    return (int8_t)fminf(fmaxf(t, -7.f), 7.f);
}

__global__ void __launch_bounds__(256) k_quant_all(
        const float* __restrict__ w1, const float* __restrict__ w2,
        const float* __restrict__ wl1, const float* __restrict__ wl2) {
    int b = blockIdx.x, tid = threadIdx.x;
    if (b < 6400) {                               // wl1 char4
        float s = __fdiv_rn(__uint_as_float(g_absmax[2]), 7.0f);
        int i = b * 256 + tid;
        float4 v = ((const float4*)wl1)[i];
        char4 o;
        o.x = qw7(v.x, s); o.y = qw7(v.y, s);
        o.z = qw7(v.z, s); o.w = qw7(v.w, s);
        ((char4*)g_wl1q)[i] = o;
    } else if (b < 6440) {                        // wl2 char4
        float s = __fdiv_rn(__uint_as_float(g_absmax[3]), 7.0f);
        int i = (b - 6400) * 256 + tid;
        float4 v = ((const float4*)wl2)[i];
        char4 o;
        o.x = qw7(v.x, s); o.y = qw7(v.y, s);
        o.z = qw7(v.z, s); o.w = qw7(v.w, s);
        ((char4*)g_wl2q)[i] = o;
    } else if (b < 6512) {                        // w2 relayout
        float s = __fdiv_rn(__uint_as_float(g_absmax[1]), 7.0f);
        int i = (b - 6440) * 256 + tid;           // < 18432
        int o = i / 288, rem = i % 288, ci = rem / 9, tap = rem % 9;
        g_w2q[((tap * 8 + (ci >> 2)) * 64 + o) * 4 + (ci & 3)] = qw7(w2[i], s);
    } else {                                      // w1
        float s = __fdiv_rn(__uint_as_float(g_absmax[0]), 7.0f);
        for (int i = tid; i < 288; i += 256) g_w1q[i] = qw7(w1[i], s);
    }
}

// ---------------------------------------------------------------------------
// LUT build: integer accumulator -> final int8 code, same fp ops as inline.
__global__ void __launch_bounds__(256) k_lut(const float* __restrict__ ps_in,
                                             const float* __restrict__ ps_a1,
                                             const float* __restrict__ ps_a2,
                                             const float* __restrict__ ps_a3) {
    int i = blockIdx.x * 256 + threadIdx.x;
    float s_in = ps_in[0];
    float sw1 = __fdiv_rn(__uint_as_float(g_absmax[0]), 7.0f);
    float sw2 = __fdiv_rn(__uint_as_float(g_absmax[1]), 7.0f);
    float sw3 = __fdiv_rn(__uint_as_float(g_absmax[2]), 7.0f);
    if (i < 1009) {                               // conv1: quant(s_a1)+requant
        float s_a1 = ps_a1[0];
        float v = (float)(i - 504) * (s_in * sw1);
        float t = rintf(__fdiv_rn(v, s_a1));
        t = fminf(fmaxf(t, 0.f), 15.f);
        float t2 = rintf(__fdiv_rn(t * s_a1, s_in));
        g_lut1[i] = (int8_t)fminf(fmaxf(t2, -8.f), 7.f);
    }
    if (i < 32257) {                              // conv2: quant(s_a2)+requant
        float s_a2 = ps_a2[0];
        float v = (float)(i - 16128) * (s_in * sw2);
        float t = rintf(__fdiv_rn(v, s_a2));
        t = fminf(fmaxf(t, 0.f), 15.f);
        float t2 = rintf(__fdiv_rn(t * s_a2, s_in));
        g_lut2[i] = (int8_t)fminf(fmaxf(t2, -8.f), 7.f);
    }
    if (i < 179201) {                             // fc1: relu-quant(s_a3)
        float s_a3 = ps_a3[0];
        float v = (float)(i - 89600) * (s_in * sw3);
        float t = rintf(__fdiv_rn(v, s_a3));
        g_lut3[i] = (int8_t)fminf(fmaxf(t, 0.f), 15.f);
    }
}

// ---------------------------------------------------------------------------
// conv1: quantize x -> 3x3 conv via dp4a (packed rows + pre-shifted weight
// words) -> integer pool-max -> LUT. One block per image.
__global__ void __launch_bounds__(256) k_conv1(const float* __restrict__ x,
                                               const float* __restrict__ ps_in) {
    __shared__ __align__(4) int8_t sx[28 * 32];   // row stride 32 bytes
    __shared__ int swa[32][3], swb[32][3];        // (w0,w1,w2,0) / (0,w0,w1,w2)
    __shared__ int8_t slut[1009];
    int b = blockIdx.x, tid = threadIdx.x;
    float s_in = ps_in[0];
    const float* xb = x + b * 784;
    for (int i = tid; i < 784; i += 256) {
        float t = rintf(__fdiv_rn(xb[i], s_in));
        t = fminf(fmaxf(t, -8.f), 7.f);
        sx[(i / 28) * 32 + (i % 28)] = (int8_t)t;
    }
    if (tid < 96) {
        int c = tid / 3, ky = tid % 3;
        int w0 = (int)g_w1q[c * 9 + ky * 3] & 0xff;
        int w1 = (int)g_w1q[c * 9 + ky * 3 + 1] & 0xff;
        int w2 = (int)g_w1q[c * 9 + ky * 3 + 2] & 0xff;
        swa[c][ky] = w0 | (w1 << 8) | (w2 << 16);
        swb[c][ky] = (w0 << 8) | (w1 << 16) | (w2 << 24);
    }
    for (int i = tid; i < 1009; i += 256) slut[i] = g_lut1[i];
    __syncthreads();

    int ch = tid & 31, wq = tid >> 5;             // channel fixed per thread
    int wA0 = swa[ch][0], wA1 = swa[ch][1], wA2 = swa[ch][2];
    int wB0 = swb[ch][0], wB1 = swb[ch][1], wB2 = swb[ch][2];
    const int* sxw = (const int*)sx;

    for (int it = 0; it < 22; it++) {
        int win = wq + it * 8;                    // uniform per warp
        if (win >= 169) break;
        int ph = win / 13, pw = win % 13;
        int bytec = 2 * pw, widx = bytec >> 2, sh = bytec & 3;  // sh in {0,2}
        int r0 = 2 * ph;
        int rows[4];
#pragma unroll
        for (int r = 0; r < 4; r++) {
            int u = sxw[(r0 + r) * 8 + widx];
            int v = sxw[(r0 + r) * 8 + widx + 1]; // widx<=6 -> in bounds
            rows[r] = sh ? __byte_perm(u, v, 0x5432) : u;
        }
        int a00 = __dp4a(rows[0], wA0, __dp4a(rows[1], wA1, __dp4a(rows[2], wA2, 0)));
        int a01 = __dp4a(rows[0], wB0, __dp4a(rows[1], wB1, __dp4a(rows[2], wB2, 0)));
        int a10 = __dp4a(rows[1], wA0, __dp4a(rows[2], wA1, __dp4a(rows[3], wA2, 0)));
        int a11 = __dp4a(rows[1], wB0, __dp4a(rows[2], wB1, __dp4a(rows[3], wB2, 0)));
        int amax = max(max(a00, a01), max(a10, a11));
        g_a1[(b * 169 + win) * 32 + ch] = slut[amax + 504];
    }
}

// ---------------------------------------------------------------------------
// conv2 (dp4a): 3x3x32 conv -> integer pool-max -> LUT -> g_a2.
__global__ void __launch_bounds__(256) k_conv2() {
    __shared__ __align__(16) int8_t sa[5408];    // 13*13*32 NHWC
    __shared__ __align__(16) int8_t swq[18432];  // [tap][cg][oc][4]
    int b = blockIdx.x, tid = threadIdx.x;
    {
        const int4* src = (const int4*)(g_a1 + b * 5408);
        int4* dst = (int4*)sa;
        for (int i = tid; i < 338; i += 256) dst[i] = src[i];
        const int4* ws = (const int4*)g_w2q;
        int4* wd = (int4*)swq;
        for (int i = tid; i < 1152; i += 256) wd[i] = ws[i];
    }
    __syncthreads();
    if (tid >= 200) return;

    int win = tid >> 3, tn = tid & 7;     // 25 windows x 8 channel-groups
    int ph = win / 5, pw = win % 5;
    const int* aw = (const int*)sa;
    const int* ww = (const int*)swq;

    int acc[4][8];
#pragma unroll
    for (int i = 0; i < 4; i++)
#pragma unroll
        for (int j = 0; j < 8; j++) acc[i][j] = 0;

#pragma unroll
    for (int ky = 0; ky < 3; ky++) {
#pragma unroll
        for (int kx = 0; kx < 3; kx++) {
            int base[4];
#pragma unroll
            for (int i = 0; i < 4; i++) {
                int dy = i >> 1, dx = i & 1;
                base[i] = ((2 * ph + dy + ky) * 13 + (2 * pw + dx + kx)) * 8;
            }
            int k9 = ky * 3 + kx;
#pragma unroll
            for (int cg = 0; cg < 8; cg++) {
                int av[4];
#pragma unroll
                for (int i = 0; i < 4; i++) av[i] = aw[base[i] + cg];
#pragma unroll
                for (int j = 0; j < 8; j++) {
                    int wv = ww[(k9 * 8 + cg) * 64 + tn * 8 + j];
#pragma unroll
                    for (int i = 0; i < 4; i++)
                        acc[i][j] = __dp4a(av[i], wv, acc[i][j]);
                }
            }
        }
    }
#pragma unroll
    for (int j = 0; j < 8; j++) {
        int qm = max(max(acc[0][j], acc[1][j]), max(acc[2][j], acc[3][j]));
        g_a2[b * 1600 + (tn * 8 + j) * 25 + ph * 5 + pw] = g_lut2[qm + 16128];
    }
}

// ---------------------------------------------------------------------------
// FC1 via int8 mma.sync m16n8k32. BM=128 BN=128 BK=64, LUT epilogue.
__device__ __forceinline__ void ldm_x4(uint32_t addr, uint32_t* r) {
    asm volatile("ldmatrix.sync.aligned.m8n8.x4.shared.b16 {%0,%1,%2,%3}, [%4];"
                 : "=r"(r[0]), "=r"(r[1]), "=r"(r[2]), "=r"(r[3]) : "r"(addr));
}

__device__ __forceinline__ void mma_s8(int* c, const uint32_t* a,
                                       uint32_t b0, uint32_t b1) {
    asm volatile(
        "mma.sync.aligned.m16n8k32.row.col.s32.s8.s8.s32 "
        "{%0,%1,%2,%3}, {%4,%5,%6,%7}, {%8,%9}, {%0,%1,%2,%3};"
        : "+r"(c[0]), "+r"(c[1]), "+r"(c[2]), "+r"(c[3])
        : "r"(a[0]), "r"(a[1]), "r"(a[2]), "r"(a[3]), "r"(b0), "r"(b1));
}

__global__ void __launch_bounds__(256, 2) k_fc1() {
    __shared__ __align__(16) int8_t As[128 * 64];  // [row][plane*16B] swizzled
    __shared__ __align__(16) int8_t Bs[128 * 64];
    int tid = threadIdx.x, lane = tid & 31, wid = tid >> 5;
    int wm = wid >> 2, wn = wid & 3;               // warp tile 64x32
    int m0 = blockIdx.y * 128, n0 = blockIdx.x * 128;

    int srow = tid >> 2, sp = tid & 3;
    int spp = sp ^ ((srow >> 1) & 3);
    const int8_t* agp = g_a2 + (m0 + srow) * 1600 + sp * 16;
    const int8_t* bgp = g_wl1q + (n0 + srow) * 1600 + sp * 16;
    int soff = (srow * 4 + spp) * 16;

    uint32_t sm_a = (uint32_t)__cvta_generic_to_shared(As);
    uint32_t sm_b = (uint32_t)__cvta_generic_to_shared(Bs);

    int acc[4][4][4];
#pragma unroll
    for (int i = 0; i < 4; i++)
#pragma unroll
        for (int j = 0; j < 4; j++)
#pragma unroll
            for (int k = 0; k < 4; k++) acc[i][j][k] = 0;

    int rl = lane & 15, ph = lane >> 4;
    uint32_t a_addr[4], b_addr[2];
#pragma unroll
    for (int mt = 0; mt < 4; mt++) {
        int r = wm * 64 + mt * 16 + rl;
        int pp = ph ^ ((r >> 1) & 3);
        a_addr[mt] = sm_a + (r * 4 + pp) * 16;
    }
#pragma unroll
    for (int bt = 0; bt < 2; bt++) {
        int n = wn * 32 + bt * 16 + rl;
        int pp = ph ^ ((n >> 1) & 3);
        b_addr[bt] = sm_b + (n * 4 + pp) * 16;
    }

    int4 ra0 = *(const int4*)agp;
    int4 ra1 = *(const int4*)(agp + 64 * 1600);
    int4 rb0 = *(const int4*)bgp;
    int4 rb1 = *(const int4*)(bgp + 64 * 1600);

    for (int ch = 0; ch < 25; ch++) {
        __syncthreads();
        *(int4*)(As + soff) = ra0;
        *(int4*)(As + soff + 4096) = ra1;
        *(int4*)(Bs + soff) = rb0;
        *(int4*)(Bs + soff + 4096) = rb1;
        __syncthreads();
        agp += 64; bgp += 64;
        if (ch < 24) {
            ra0 = *(const int4*)agp;
            ra1 = *(const int4*)(agp + 64 * 1600);
            rb0 = *(const int4*)bgp;
            rb1 = *(const int4*)(bgp + 64 * 1600);
        }
#pragma unroll
        for (int ks = 0; ks < 2; ks++) {
            uint32_t kx = ks ? 32u : 0u;           // plane ^2 == byte ^32
            uint32_t af[4][4], bf[2][4];
#pragma unroll
            for (int mt = 0; mt < 4; mt++) ldm_x4(a_addr[mt] ^ kx, af[mt]);
#pragma unroll
            for (int bt = 0; bt < 2; bt++) ldm_x4(b_addr[bt] ^ kx, bf[bt]);
#pragma unroll
            for (int mt = 0; mt < 4; mt++)
#pragma unroll
                for (int nt = 0; nt < 4; nt++)
                    mma_s8(acc[mt][nt], af[mt],
                           bf[nt >> 1][nt & 1], bf[nt >> 1][(nt & 1) + 2]);
        }
    }

    int g = lane >> 2, t4 = lane & 3;
#pragma unroll
    for (int mt = 0; mt < 4; mt++) {
#pragma unroll
        for (int nt = 0; nt < 4; nt++) {
            int mrow = m0 + wm * 64 + mt * 16 + g;
            int ncol = n0 + wn * 32 + nt * 8 + t4 * 2;
#pragma unroll
            for (int h = 0; h < 2; h++) {
                char2 o;
                o.x = g_lut3[acc[mt][nt][2 * h] + 89600];
                o.y = g_lut3[acc[mt][nt][2 * h + 1] + 89600];
                *(char2*)(g_a3 + (mrow + 8 * h) * 4096 + ncol) = o;
            }
        }
    }
}

// ---------------------------------------------------------------------------
// FC2: [1024,4096] x [10,4096]^T -> f32 out. One block per image row.
__global__ void __launch_bounds__(128) k_fc2(float* __restrict__ out,
                                             const float* __restrict__ ps_a3) {
    __shared__ int red[4][10];
    int b = blockIdx.x, tid = threadIdx.x;
    const int* aw = (const int*)g_a3 + b * 1024;
    const int* wp = (const int*)g_wl2q;
    int acc[10];
#pragma unroll
    for (int n = 0; n < 10; n++) acc[n] = 0;
    for (int k = tid; k < 1024; k += 128) {
        int a = aw[k];
#pragma unroll
        for (int n = 0; n < 10; n++) acc[n] = __dp4a(a, wp[n * 1024 + k], acc[n]);
    }
#pragma unroll
    for (int n = 0; n < 10; n++)
#pragma unroll
        for (int o = 16; o > 0; o >>= 1)
            acc[n] += __shfl_xor_sync(0xffffffffu, acc[n], o);
    if ((tid & 31) == 0) {
        int w = tid >> 5;
#pragma unroll
        for (int n = 0; n < 10; n++) red[w][n] = acc[n];
    }
    __syncthreads();
    if (tid < 10) {
        int s = red[0][tid] + red[1][tid] + red[2][tid] + red[3][tid];
        float s_a3 = ps_a3[0];
        float s_w = __fdiv_rn(__uint_as_float(g_absmax[3]), 7.0f);
        out[b * 10 + tid] = (float)s * (s_a3 * s_w);
    }
}

// ---------------------------------------------------------------------------
extern "C" void kernel_launch(void* const* d_in, const int* in_sizes, int n_in,
                              void* d_out, int out_size) {
    const float* x    = (const float*)d_in[0];
    const float* w1   = (const float*)d_in[1];
    const float* w2   = (const float*)d_in[2];
    const float* wl1  = (const float*)d_in[3];
    const float* wl2  = (const float*)d_in[4];
    const float* s_in = (const float*)d_in[5];
    const float* s_a1 = (const float*)d_in[6];
    const float* s_a2 = (const float*)d_in[7];
    const float* s_a3 = (const float*)d_in[8];
    float* out = (float*)d_out;
    (void)in_sizes; (void)n_in; (void)out_size;

    k_init<<<1, 32>>>();
    k_absmax_all<<<2107, 256>>>(w1, w2, wl1, wl2);
    k_quant_all<<<6513, 256>>>(w1, w2, wl1, wl2);
    k_lut<<<701, 256>>>(s_in, s_a1, s_a2, s_a3);
    k_conv1<<<1024, 256>>>(x, s_in);
    k_conv2<<<1024, 256>>>();
    k_fc1<<<dim3(4096 / 128, 1024 / 128), 256>>>();
    k_fc2<<<1024, 128>>>(out, s_a3);
}

// round 6
// speedup vs baseline: 1.5245x; 1.0307x over previous
#include <cuda_runtime.h>
#include <cstdint>

// ---------------------------------------------------------------------------
// Quantized LeNet, B=1024. conv1 dp4a, conv2 + FC1 int8 mma.sync tensor cores.
// Pool-max commutes with monotone quantization -> integer max first; quant
// chains precomputed into integer->int8 LUTs (exact).
// ---------------------------------------------------------------------------

#define DEVBUF __device__ __align__(16)

__device__ unsigned g_absmax[4];                 // |w| max bits: w1,w2,wl1,wl2
DEVBUF int8_t g_w1q [32 * 9];                    // [oc][tap]
DEVBUF int8_t g_w2m [64 * 384];                  // mma B: [oc][24 planes] swizzled
DEVBUF int8_t g_wl1q[4096 * 1600];               // row-major [n][k]
DEVBUF int8_t g_wl2q[10 * 4096];                 // row-major [n][k]
DEVBUF int8_t g_a1  [1024 * 13 * 13 * 32];       // conv1 out, NHWC codes [-8,7]
DEVBUF int8_t g_a2  [1024 * 1600];               // conv2 out, NCHW-flat codes
DEVBUF int8_t g_a3  [1024 * 4096];               // fc1 out, codes [0,15]
DEVBUF int8_t g_lut1[1009];                      // conv1 acc -> code  (+504)
DEVBUF int8_t g_lut2[32257];                     // conv2 acc -> code  (+16128)
DEVBUF int8_t g_lut3[179201];                    // fc1  acc -> code  (+89600)

// ---------------------------------------------------------------------------
__global__ void k_init() {
    if (threadIdx.x < 4) g_absmax[threadIdx.x] = 0u;
}

__global__ void __launch_bounds__(256) k_absmax_all(
        const float* __restrict__ w1, const float* __restrict__ w2,
        const float* __restrict__ wl1, const float* __restrict__ wl2) {
    int b = blockIdx.x, tid = threadIdx.x;
    float m = 0.f;
    int slot;
    if (b < 2048) {                               // wl1: 1638400 float4
        slot = 2;
        const float4* p = (const float4*)wl1;
        for (int i = b * 256 + tid; i < 1638400; i += 2048 * 256) {
            float4 v = p[i];
            m = fmaxf(fmaxf(fabsf(v.x), fabsf(v.y)),
                      fmaxf(fabsf(v.z), fabsf(v.w)));
        }
    } else if (b < 2088) {                        // wl2: 10240 float4
        slot = 3;
        float4 v = ((const float4*)wl2)[(b - 2048) * 256 + tid];
        m = fmaxf(fmaxf(fabsf(v.x), fabsf(v.y)), fmaxf(fabsf(v.z), fabsf(v.w)));
    } else if (b < 2106) {                        // w2: 4608 float4
        slot = 1;
        float4 v = ((const float4*)w2)[(b - 2088) * 256 + tid];
        m = fmaxf(fmaxf(fabsf(v.x), fabsf(v.y)), fmaxf(fabsf(v.z), fabsf(v.w)));
    } else {                                      // w1: 72 float4
        slot = 0;
        if (tid < 72) {
            float4 v = ((const float4*)w1)[tid];
            m = fmaxf(fmaxf(fabsf(v.x), fabsf(v.y)),
                      fmaxf(fabsf(v.z), fabsf(v.w)));
        }
    }
#pragma unroll
    for (int o = 16; o > 0; o >>= 1)
        m = fmaxf(m, __shfl_xor_sync(0xffffffffu, m, o));
    if ((tid & 31) == 0)
        atomicMax(&g_absmax[slot], __float_as_uint(m));
}

__device__ __forceinline__ int8_t qw7(float x, float s) {
    float t = rintf(__fdiv_rn(x, s));
    return (int8_t)fminf(fmaxf(t, -7.f), 7.f);
}

// Weight quant + w2 mma-relayout + LUT build, one kernel.
__global__ void __launch_bounds__(256) k_quant_all(
        const float* __restrict__ w1, const float* __restrict__ w2,
        const float* __restrict__ wl1, const float* __restrict__ wl2,
        const float* __restrict__ ps_in, const float* __restrict__ ps_a1,
        const float* __restrict__ ps_a2, const float* __restrict__ ps_a3) {
    int b = blockIdx.x, tid = threadIdx.x;
    if (b < 6400) {                               // wl1 char4
        float s = __fdiv_rn(__uint_as_float(g_absmax[2]), 7.0f);
        int i = b * 256 + tid;
        float4 v = ((const float4*)wl1)[i];
        char4 o;
        o.x = qw7(v.x, s); o.y = qw7(v.y, s);
        o.z = qw7(v.z, s); o.w = qw7(v.w, s);
        ((char4*)g_wl1q)[i] = o;
    } else if (b < 6440) {                        // wl2 char4
        float s = __fdiv_rn(__uint_as_float(g_absmax[3]), 7.0f);
        int i = (b - 6400) * 256 + tid;
        float4 v = ((const float4*)wl2)[i];
        char4 o;
        o.x = qw7(v.x, s); o.y = qw7(v.y, s);
        o.z = qw7(v.z, s); o.w = qw7(v.w, s);
        ((char4*)g_wl2q)[i] = o;
    } else if (b < 6512) {                        // w2 -> swizzled mma layout
        float s = __fdiv_rn(__uint_as_float(g_absmax[1]), 7.0f);
        int i = (b - 6440) * 256 + tid;           // < 18432
        int o = i / 288, rem = i % 288, ci = rem / 9, tap = rem % 9;
        int k = tap * 32 + ci;
        int p = k >> 4;
        g_w2m[o * 384 + (((p ^ (o & 7)) << 4) | (k & 15))] = qw7(w2[i], s);
    } else if (b == 6512) {                       // w1
        float s = __fdiv_rn(__uint_as_float(g_absmax[0]), 7.0f);
        for (int i = tid; i < 288; i += 256) g_w1q[i] = qw7(w1[i], s);
    } else {                                      // LUT build
        int i = (b - 6513) * 256 + tid;
        float s_in = ps_in[0];
        float sw1 = __fdiv_rn(__uint_as_float(g_absmax[0]), 7.0f);
        float sw2 = __fdiv_rn(__uint_as_float(g_absmax[1]), 7.0f);
        float sw3 = __fdiv_rn(__uint_as_float(g_absmax[2]), 7.0f);
        if (i < 1009) {
            float s_a1 = ps_a1[0];
            float v = (float)(i - 504) * (s_in * sw1);
            float t = rintf(__fdiv_rn(v, s_a1));
            t = fminf(fmaxf(t, 0.f), 15.f);
            float t2 = rintf(__fdiv_rn(t * s_a1, s_in));
            g_lut1[i] = (int8_t)fminf(fmaxf(t2, -8.f), 7.f);
        }
        if (i < 32257) {
            float s_a2 = ps_a2[0];
            float v = (float)(i - 16128) * (s_in * sw2);
            float t = rintf(__fdiv_rn(v, s_a2));
            t = fminf(fmaxf(t, 0.f), 15.f);
            float t2 = rintf(__fdiv_rn(t * s_a2, s_in));
            g_lut2[i] = (int8_t)fminf(fmaxf(t2, -8.f), 7.f);
        }
        if (i < 179201) {
            float s_a3 = ps_a3[0];
            float v = (float)(i - 89600) * (s_in * sw3);
            float t = rintf(__fdiv_rn(v, s_a3));
            g_lut3[i] = (int8_t)fminf(fmaxf(t, 0.f), 15.f);
        }
    }
}

// ---------------------------------------------------------------------------
// conv1: quantize x -> 3x3 conv via dp4a -> integer pool-max -> LUT.
__global__ void __launch_bounds__(256) k_conv1(const float* __restrict__ x,
                                               const float* __restrict__ ps_in) {
    __shared__ __align__(4) int8_t sx[28 * 32];   // row stride 32 bytes
    __shared__ int swa[32][3], swb[32][3];
    __shared__ int8_t slut[1009];
    int b = blockIdx.x, tid = threadIdx.x;
    float s_in = ps_in[0];
    const float* xb = x + b * 784;
    for (int i = tid; i < 784; i += 256) {
        float t = rintf(__fdiv_rn(xb[i], s_in));
        t = fminf(fmaxf(t, -8.f), 7.f);
        sx[(i / 28) * 32 + (i % 28)] = (int8_t)t;
    }
    if (tid < 96) {
        int c = tid / 3, ky = tid % 3;
        int w0 = (int)g_w1q[c * 9 + ky * 3] & 0xff;
        int w1 = (int)g_w1q[c * 9 + ky * 3 + 1] & 0xff;
        int w2 = (int)g_w1q[c * 9 + ky * 3 + 2] & 0xff;
        swa[c][ky] = w0 | (w1 << 8) | (w2 << 16);
        swb[c][ky] = (w0 << 8) | (w1 << 16) | (w2 << 24);
    }
    for (int i = tid; i < 1009; i += 256) slut[i] = g_lut1[i];
    __syncthreads();

    int ch = tid & 31, wq = tid >> 5;
    int wA0 = swa[ch][0], wA1 = swa[ch][1], wA2 = swa[ch][2];
    int wB0 = swb[ch][0], wB1 = swb[ch][1], wB2 = swb[ch][2];
    const int* sxw = (const int*)sx;

    for (int it = 0; it < 22; it++) {
        int win = wq + it * 8;
        if (win >= 169) break;
        int ph = win / 13, pw = win % 13;
        int bytec = 2 * pw, widx = bytec >> 2, sh = bytec & 3;
        int r0 = 2 * ph;
        int rows[4];
#pragma unroll
        for (int r = 0; r < 4; r++) {
            int u = sxw[(r0 + r) * 8 + widx];
            int v = sxw[(r0 + r) * 8 + widx + 1];
            rows[r] = sh ? __byte_perm(u, v, 0x5432) : u;
        }
        int a00 = __dp4a(rows[0], wA0, __dp4a(rows[1], wA1, __dp4a(rows[2], wA2, 0)));
        int a01 = __dp4a(rows[0], wB0, __dp4a(rows[1], wB1, __dp4a(rows[2], wB2, 0)));
        int a10 = __dp4a(rows[1], wA0, __dp4a(rows[2], wA1, __dp4a(rows[3], wA2, 0)));
        int a11 = __dp4a(rows[1], wB0, __dp4a(rows[2], wB1, __dp4a(rows[3], wB2, 0)));
        int amax = max(max(a00, a01), max(a10, a11));
        g_a1[(b * 169 + win) * 32 + ch] = slut[amax + 504];
    }
}

// ---------------------------------------------------------------------------
__device__ __forceinline__ void ldm_x4(uint32_t addr, uint32_t* r) {
    asm volatile("ldmatrix.sync.aligned.m8n8.x4.shared.b16 {%0,%1,%2,%3}, [%4];"
                 : "=r"(r[0]), "=r"(r[1]), "=r"(r[2]), "=r"(r[3]) : "r"(addr));
}

__device__ __forceinline__ void mma_s8(int* c, const uint32_t* a,
                                       uint32_t b0, uint32_t b1) {
    asm volatile(
        "mma.sync.aligned.m16n8k32.row.col.s32.s8.s8.s32 "
        "{%0,%1,%2,%3}, {%4,%5,%6,%7}, {%8,%9}, {%0,%1,%2,%3};"
        : "+r"(c[0]), "+r"(c[1]), "+r"(c[2]), "+r"(c[3])
        : "r"(a[0]), "r"(a[1]), "r"(a[2]), "r"(a[3]), "r"(b0), "r"(b1));
}

// ---------------------------------------------------------------------------
// conv2 via mma: per image im2col A[112 rows x 288 k] (row = win*4+dp),
// B = g_w2m [64 x 288] pre-swizzled. Rows stride 384B, plane p^(row&7).
// Pool: rows of one window live in lanes l, l^4, l^8 -> shfl-max, then LUT.
__global__ void __launch_bounds__(256, 2) k_conv2() {
    extern __shared__ __align__(16) int8_t dyn[];
    int8_t* Asm = dyn;                 // 112*384 = 43008
    int8_t* Bsm = dyn + 43008;         // 64*384  = 24576
    int b = blockIdx.x, tid = threadIdx.x;

    {   // stage B (swizzle baked in global)
        const int4* src = (const int4*)g_w2m;
        int4* dst = (int4*)Bsm;
#pragma unroll
        for (int i = 0; i < 6; i++) dst[tid + 256 * i] = src[tid + 256 * i];
    }
    {   // stage A: im2col from g_a1 (NHWC, L1-resident), swizzled STS.128
        const int8_t* img = g_a1 + b * 5408;
        for (int idx = tid; idx < 1800; idx += 256) {
            int r = idx / 18, p = idx - r * 18;
            int win = r >> 2, dp = r & 3;
            int ph = win / 5, pw = win - ph * 5;
            int tap = p >> 1, ky = tap / 3, kx = tap - ky * 3;
            int oy = 2 * ph + (dp >> 1) + ky, ox = 2 * pw + (dp & 1) + kx;
            int4 v = *(const int4*)(img + (oy * 13 + ox) * 32 + (p & 1) * 16);
            *(int4*)(Asm + r * 384 + (((p ^ (r & 7)) << 4))) = v;
        }
    }
    __syncthreads();

    int lane = tid & 31, wid = tid >> 5;
    if (wid >= 7) return;                         // 7 m-tiles (112 rows)
    int mt = wid;
    int rl = lane & 15, phh = lane >> 4;
    uint32_t smA = (uint32_t)__cvta_generic_to_shared(Asm);
    uint32_t smB = (uint32_t)__cvta_generic_to_shared(Bsm);
    int ra = mt * 16 + rl;
    uint32_t aBase = smA + ra * 384, aXor = (uint32_t)((ra & 7) << 4);
    uint32_t bBase[4], bXor[4];
#pragma unroll
    for (int bt = 0; bt < 4; bt++) {
        int rb = bt * 16 + rl;
        bBase[bt] = smB + rb * 384;
        bXor[bt] = (uint32_t)((rb & 7) << 4);
    }

    int acc[8][4];
#pragma unroll
    for (int i = 0; i < 8; i++)
#pragma unroll
        for (int j = 0; j < 4; j++) acc[i][j] = 0;

#pragma unroll
    for (int s = 0; s < 9; s++) {
        uint32_t pb = (uint32_t)((2 * s + phh) << 4);
        uint32_t af[4];
        ldm_x4(aBase + (pb ^ aXor), af);
        uint32_t bf[4][4];
#pragma unroll
        for (int bt = 0; bt < 4; bt++) ldm_x4(bBase[bt] + (pb ^ bXor[bt]), bf[bt]);
#pragma unroll
        for (int nt = 0; nt < 8; nt++)
            mma_s8(acc[nt], af, bf[nt >> 1][nt & 1], bf[nt >> 1][(nt & 1) + 2]);
    }

    // epilogue: shfl-max over the 4 rows of each pool window, then LUT.
    int t4 = lane & 3;
    int winA = mt * 4 + (lane >> 4);              // rows g   (g>>2 = lane>>4)
    int winB = winA + 2;                          // rows g+8
    bool st = ((lane >> 2) & 3) == 0;
    int8_t* dst = g_a2 + b * 1600;
#pragma unroll
    for (int nt = 0; nt < 8; nt++) {
        int m0 = acc[nt][0], m1 = acc[nt][1], m2 = acc[nt][2], m3 = acc[nt][3];
        m0 = max(m0, __shfl_xor_sync(0xffffffffu, m0, 4));
        m0 = max(m0, __shfl_xor_sync(0xffffffffu, m0, 8));
        m1 = max(m1, __shfl_xor_sync(0xffffffffu, m1, 4));
        m1 = max(m1, __shfl_xor_sync(0xffffffffu, m1, 8));
        m2 = max(m2, __shfl_xor_sync(0xffffffffu, m2, 4));
        m2 = max(m2, __shfl_xor_sync(0xffffffffu, m2, 8));
        m3 = max(m3, __shfl_xor_sync(0xffffffffu, m3, 4));
        m3 = max(m3, __shfl_xor_sync(0xffffffffu, m3, 8));
        if (st) {
            int col = nt * 8 + t4 * 2;
            if (winA < 25) {
                dst[col * 25 + winA]       = g_lut2[m0 + 16128];
                dst[(col + 1) * 25 + winA] = g_lut2[m1 + 16128];
            }
            if (winB < 25) {
                dst[col * 25 + winB]       = g_lut2[m2 + 16128];
                dst[(col + 1) * 25 + winB] = g_lut2[m3 + 16128];
            }
        }
    }
}

// ---------------------------------------------------------------------------
// FC1 via int8 mma m16n8k32, BM=128 BN=128 BK=64, double-buffered smem
// (one barrier per chunk), LUT epilogue.
__global__ void __launch_bounds__(256, 2) k_fc1() {
    __shared__ __align__(16) int8_t As[2][8192];
    __shared__ __align__(16) int8_t Bs[2][8192];
    int tid = threadIdx.x, lane = tid & 31, wid = tid >> 5;
    int wm = wid >> 2, wn = wid & 3;
    int m0 = blockIdx.y * 128, n0 = blockIdx.x * 128;

    int srow = tid >> 2, sp = tid & 3;
    int spp = sp ^ ((srow >> 1) & 3);
    const int8_t* agp = g_a2 + (m0 + srow) * 1600 + sp * 16;
    const int8_t* bgp = g_wl1q + (n0 + srow) * 1600 + sp * 16;
    int soff = (srow * 4 + spp) * 16;

    uint32_t sm_a = (uint32_t)__cvta_generic_to_shared(As[0]);
    uint32_t sm_b = (uint32_t)__cvta_generic_to_shared(Bs[0]);

    int acc[4][4][4];
#pragma unroll
    for (int i = 0; i < 4; i++)
#pragma unroll
        for (int j = 0; j < 4; j++)
#pragma unroll
            for (int k = 0; k < 4; k++) acc[i][j][k] = 0;

    int rl = lane & 15, ph = lane >> 4;
    uint32_t a_addr[4], b_addr[2];
#pragma unroll
    for (int mt = 0; mt < 4; mt++) {
        int r = wm * 64 + mt * 16 + rl;
        int pp = ph ^ ((r >> 1) & 3);
        a_addr[mt] = sm_a + (r * 4 + pp) * 16;
    }
#pragma unroll
    for (int bt = 0; bt < 2; bt++) {
        int n = wn * 32 + bt * 16 + rl;
        int pp = ph ^ ((n >> 1) & 3);
        b_addr[bt] = sm_b + (n * 4 + pp) * 16;
    }

    // prologue: chunk 0 -> buf 0
    int4 ra0 = *(const int4*)agp;
    int4 ra1 = *(const int4*)(agp + 64 * 1600);
    int4 rb0 = *(const int4*)bgp;
    int4 rb1 = *(const int4*)(bgp + 64 * 1600);
    *(int4*)(As[0] + soff) = ra0;
    *(int4*)(As[0] + soff + 4096) = ra1;
    *(int4*)(Bs[0] + soff) = rb0;
    *(int4*)(Bs[0] + soff + 4096) = rb1;
    agp += 64; bgp += 64;
    __syncthreads();

    for (int chk = 0; chk < 25; chk++) {
        if (chk < 24) {                            // prefetch next chunk
            ra0 = *(const int4*)agp;
            ra1 = *(const int4*)(agp + 64 * 1600);
            rb0 = *(const int4*)bgp;
            rb1 = *(const int4*)(bgp + 64 * 1600);
            agp += 64; bgp += 64;
        }
        uint32_t kbuf = (uint32_t)((chk & 1) * 8192);
#pragma unroll
        for (int ks = 0; ks < 2; ks++) {
            uint32_t kx = (ks ? 32u : 0u) + kbuf;
            uint32_t af[4][4], bf[2][4];
#pragma unroll
            for (int mt = 0; mt < 4; mt++) ldm_x4((a_addr[mt] ^ (ks ? 32u : 0u)) + kbuf, af[mt]);
#pragma unroll
            for (int bt = 0; bt < 2; bt++) ldm_x4((b_addr[bt] ^ (ks ? 32u : 0u)) + kbuf, bf[bt]);
            (void)kx;
#pragma unroll
            for (int mt = 0; mt < 4; mt++)
#pragma unroll
                for (int nt = 0; nt < 4; nt++)
                    mma_s8(acc[mt][nt], af[mt],
                           bf[nt >> 1][nt & 1], bf[nt >> 1][(nt & 1) + 2]);
        }
        if (chk < 24) {                            // store into other buffer
            int nb = (chk + 1) & 1;
            *(int4*)(As[nb] + soff) = ra0;
            *(int4*)(As[nb] + soff + 4096) = ra1;
            *(int4*)(Bs[nb] + soff) = rb0;
            *(int4*)(Bs[nb] + soff + 4096) = rb1;
            __syncthreads();
        }
    }

    int g = lane >> 2, t4 = lane & 3;
#pragma unroll
    for (int mt = 0; mt < 4; mt++) {
#pragma unroll
        for (int nt = 0; nt < 4; nt++) {
            int mrow = m0 + wm * 64 + mt * 16 + g;
            int ncol = n0 + wn * 32 + nt * 8 + t4 * 2;
#pragma unroll
            for (int h = 0; h < 2; h++) {
                char2 o;
                o.x = g_lut3[acc[mt][nt][2 * h] + 89600];
                o.y = g_lut3[acc[mt][nt][2 * h + 1] + 89600];
                *(char2*)(g_a3 + (mrow + 8 * h) * 4096 + ncol) = o;
            }
        }
    }
}

// ---------------------------------------------------------------------------
// FC2: [1024,4096] x [10,4096]^T -> f32 out. One block per image row.
__global__ void __launch_bounds__(128) k_fc2(float* __restrict__ out,
                                             const float* __restrict__ ps_a3) {
    __shared__ int red[4][10];
    int b = blockIdx.x, tid = threadIdx.x;
    const int* aw = (const int*)g_a3 + b * 1024;
    const int* wp = (const int*)g_wl2q;
    int acc[10];
#pragma unroll
    for (int n = 0; n < 10; n++) acc[n] = 0;
    for (int k = tid; k < 1024; k += 128) {
        int a = aw[k];
#pragma unroll
        for (int n = 0; n < 10; n++) acc[n] = __dp4a(a, wp[n * 1024 + k], acc[n]);
    }
#pragma unroll
    for (int n = 0; n < 10; n++)
#pragma unroll
        for (int o = 16; o > 0; o >>= 1)
            acc[n] += __shfl_xor_sync(0xffffffffu, acc[n], o);
    if ((tid & 31) == 0) {
        int w = tid >> 5;
#pragma unroll
        for (int n = 0; n < 10; n++) red[w][n] = acc[n];
    }
    __syncthreads();
    if (tid < 10) {
        int s = red[0][tid] + red[1][tid] + red[2][tid] + red[3][tid];
        float s_a3 = ps_a3[0];
        float s_w = __fdiv_rn(__uint_as_float(g_absmax[3]), 7.0f);
        out[b * 10 + tid] = (float)s * (s_a3 * s_w);
    }
}

// ---------------------------------------------------------------------------
extern "C" void kernel_launch(void* const* d_in, const int* in_sizes, int n_in,
                              void* d_out, int out_size) {
    const float* x    = (const float*)d_in[0];
    const float* w1   = (const float*)d_in[1];
    const float* w2   = (const float*)d_in[2];
    const float* wl1  = (const float*)d_in[3];
    const float* wl2  = (const float*)d_in[4];
    const float* s_in = (const float*)d_in[5];
    const float* s_a1 = (const float*)d_in[6];
    const float* s_a2 = (const float*)d_in[7];
    const float* s_a3 = (const float*)d_in[8];
    float* out = (float*)d_out;
    (void)in_sizes; (void)n_in; (void)out_size;

    cudaFuncSetAttribute(k_conv2, cudaFuncAttributeMaxDynamicSharedMemorySize,
                         43008 + 24576);

    k_init<<<1, 32>>>();
    k_absmax_all<<<2107, 256>>>(w1, w2, wl1, wl2);
    k_quant_all<<<7214, 256>>>(w1, w2, wl1, wl2, s_in, s_a1, s_a2, s_a3);
    k_conv1<<<1024, 256>>>(x, s_in);
    k_conv2<<<1024, 256, 43008 + 24576>>>();
    k_fc1<<<dim3(4096 / 128, 1024 / 128), 256>>>();
    k_fc2<<<1024, 128>>>(out, s_a3);
}